// round 4
// baseline (speedup 1.0000x reference)
#include <cuda_runtime.h>
#include <cuda_fp16.h>
#include <cstdint>

#define E_TOT      100000
#define NCHUNK     65
#define A_TILE     32768
#define B_TILE     16384
#define NTILES     782          /* ceil(100000/128) */

/* ---- tcgen05-path smem layout (relative to 1024-aligned base) ---- */
#define SM_A       0            /* 3 x 32768 = 98304 : A ring            */
#define SM_B       98304        /* 4 x 16384 = 65536 : W ring            */
#define SM_V       163840       /* 128 rows x 136 B fp16 vert = 17408    */
#define SM_TPTR    181248
#define SM_MB_A    181264       /* 3 x 8B : A-full (count 256) */
#define SM_MB_D    181288       /* 3 x 8B : mma committed      */
#define SM_MB_B    181312       /* 4 x 8B : W-chunk full       */
#define SM_END     181344

#define LAST_S     ((NCHUNK - 1) % 3)        /* 1 */
#define LAST_P     (((NCHUNK - 1) / 3) & 1)  /* 1 */

/* ---- fallback-path smem layout (relative to same base) ---- */
#define FB_X       0            /* f32 [128 k][132]  = 67584 B  */
#define FB_V       67584        /* f32 [64 v][132]   = 33792 B  */
#define FB_B       101376       /* f32 [2][64 m][132]= 67584 B  */
#define FB_S       168960       /* f32 [64 v][64 m]  = 16384 B  */

#define SMEM_DYN   (200 * 1024)

/* does this device pass have tcgen05 (arch-specific sm_103a/sm_100a)? */
#if !defined(__CUDA_ARCH__)
#  define TCPATH 1   /* host pass: parse the tcgen05 branch (not codegen'd) */
#elif defined(__CUDA_ARCH_FEAT_SM103_ALL) || defined(__CUDA_ARCH_FEAT_SM100_ALL) || \
      defined(__CUDA_ARCH_FEAT_SM101_ALL) || defined(__CUDA_ARCH_SPECIFIC__)
#  define TCPATH 1
#else
#  define TCPATH 0
#endif

/* pre-swizzled fp16 W' image: 65 chunks of [64 n x 128 k] blocked SW128 */
__device__ __align__(16) unsigned char g_Wimg[NCHUNK * B_TILE];

/* ---------------- generic helpers ---------------- */

__device__ __forceinline__ uint32_t sw128(uint32_t x) { return x ^ ((x >> 3) & 0x70u); }

__device__ __forceinline__ uint32_t smem_u32(const void* p) {
    uint32_t a;
    asm("{ .reg .u64 t; cvta.to.shared.u64 t, %1; cvt.u32.u64 %0, t; }" : "=r"(a) : "l"(p));
    return a;
}

/* pack two f32 -> f16x2; 'lo' lands in the low (memory-first) half */
__device__ __forceinline__ uint32_t pack_h2(float lo, float hi) {
    uint32_t r;
    asm("cvt.rn.f16x2.f32 %0, %1, %2;" : "=r"(r) : "f"(hi), "f"(lo));
    return r;
}

__device__ __forceinline__ uint32_t hmul2(uint32_t a, uint32_t b) {
    uint32_t r;
    asm("mul.rn.f16x2 %0, %1, %2;" : "=r"(r) : "r"(a), "r"(b));
    return r;
}

__device__ __forceinline__ void sts128(uint32_t addr, uint32_t a, uint32_t b, uint32_t c, uint32_t d) {
    asm volatile("st.shared.v4.b32 [%0], {%1, %2, %3, %4};"
                 :: "r"(addr), "r"(a), "r"(b), "r"(c), "r"(d) : "memory");
}
__device__ __forceinline__ void sts64(uint32_t addr, uint32_t a, uint32_t b) {
    asm volatile("st.shared.v2.b32 [%0], {%1, %2};" :: "r"(addr), "r"(a), "r"(b) : "memory");
}
__device__ __forceinline__ void lds64(uint32_t& a, uint32_t& b, uint32_t addr) {
    asm volatile("ld.shared.v2.b32 {%0, %1}, [%2];" : "=r"(a), "=r"(b) : "r"(addr));
}
__device__ __forceinline__ uint32_t lds32(uint32_t addr) {
    uint32_t v;
    asm volatile("ld.shared.b32 %0, [%1];" : "=r"(v) : "r"(addr));
    return v;
}

__device__ __forceinline__ void mbar_wait(uint32_t mbar, uint32_t parity) {
    asm volatile(
        "{\n\t.reg .pred P;\n\tWL_%=:\n\t"
        "mbarrier.try_wait.parity.acquire.cta.shared::cta.b64 P, [%0], %1, 0x989680;\n\t"
        "@P bra.uni WD_%=;\n\tbra.uni WL_%=;\n\tWD_%=:\n\t}"
        :: "r"(mbar), "r"(parity) : "memory");
}

/* ---------------- prep kernel: pre-swizzled fp16 W' image ---------------- */
/* chunk c<64: Wc[n,k] = W[n*64+c, k]; chunk 64: Wc[n,k] = (k<64)? b[n*64+k] : 0 */
__global__ void prep_w(const float* __restrict__ W, const float* __restrict__ b) {
    uint32_t gid = blockIdx.x * 256u + threadIdx.x;      /* 0 .. 266239 */
    uint32_t c  = gid >> 12;
    uint32_t r  = gid & 4095u;
    uint32_t n  = r >> 6;
    uint32_t k  = (r & 63u) * 2u;
    float w0, w1;
    if (c < 64u) {
        const float* s = W + ((n * 64u + c) * 128u + k);
        w0 = s[0]; w1 = s[1];
    } else if (k < 64u) {
        w0 = b[n * 64u + k]; w1 = b[n * 64u + k + 1u];
    } else {
        w0 = 0.f; w1 = 0.f;
    }
    uint32_t off = ((n >> 3) + (k >> 6) * 8u) * 1024u + (n & 7u) * 128u + (k & 63u) * 2u;
    *(uint32_t*)(g_Wimg + c * B_TILE + sw128(off)) = pack_h2(w0, w1);
}

/* ---------------- main kernel ---------------- */
__global__ void __launch_bounds__(256, 1)
edge_msg_main(const float* __restrict__ vert,
              const float* __restrict__ xedges,
              const float* __restrict__ Wg,
              const float* __restrict__ bg,
              float* __restrict__ out)
{
    extern __shared__ unsigned char smem_raw[];
    const uint32_t raw  = smem_u32(smem_raw);
    const uint32_t base = (raw + 1023u) & ~1023u;
    unsigned char* sb   = smem_raw + (base - raw);

    const int tid  = threadIdx.x;
    const int tb   = blockIdx.x * 128;

#if TCPATH
    /* ================= tcgen05 path (sm_103a) ================= */
    const int wid  = tid >> 5;
    const int lane = tid & 31;
    const int r    = tid >> 1;      /* owned A-row 0..127      */
    const int h    = tid & 1;       /* half: k in [h*64,h*64+64) */

    (void)Wg; (void)bg;

    if (tid == 0) {
        #pragma unroll
        for (int i = 0; i < 3; i++) {
            asm volatile("mbarrier.init.shared.b64 [%0], 256;" :: "r"(base + SM_MB_A + i * 8) : "memory");
            asm volatile("mbarrier.init.shared.b64 [%0], 1;"   :: "r"(base + SM_MB_D + i * 8) : "memory");
        }
        #pragma unroll
        for (int i = 0; i < 4; i++)
            asm volatile("mbarrier.init.shared.b64 [%0], 1;"   :: "r"(base + SM_MB_B + i * 8) : "memory");
    }
    if (wid == 0) {
        asm volatile("tcgen05.alloc.cta_group::1.sync.aligned.shared::cta.b32 [%0], 512;"
                     :: "r"(base + SM_TPTR) : "memory");
        asm volatile("tcgen05.relinquish_alloc_permit.cta_group::1.sync.aligned;");
    }
    __syncthreads();
    uint32_t tmem;
    asm volatile("ld.shared.b32 %0, [%1];" : "=r"(tmem) : "r"(base + SM_TPTR));

    bool is_elect = false;
    {
        uint32_t p;
        asm volatile("{\n\t.reg .pred P;\n\telect.sync _|P, 0xFFFFFFFF;\n\tselp.b32 %0, 1, 0, P;\n\t}" : "=r"(p));
        is_elect = (wid == 0) && (p != 0);
    }

    /* prefetch W chunks 0,1 */
    if (is_elect) {
        #pragma unroll
        for (int j = 0; j < 2; j++) {
            asm volatile("mbarrier.arrive.expect_tx.shared.b64 _, [%0], %1;"
                         :: "r"(base + SM_MB_B + j * 8), "r"((uint32_t)B_TILE) : "memory");
            asm volatile("cp.async.bulk.shared::cta.global.mbarrier::complete_tx::bytes [%0], [%1], %2, [%3];"
                         :: "r"(base + SM_B + j * B_TILE), "l"(g_Wimg + j * B_TILE),
                            "r"((uint32_t)B_TILE), "r"(base + SM_MB_B + j * 8) : "memory");
        }
    }

    int e = tb + r; if (e >= E_TOT) e = E_TOT - 1;

    /* stage vertices as fp16: V[r][64], row stride 136 B (bank-spread) */
    const uint32_t vb = base + SM_V;
    {
        const float4* vp = (const float4*)(vert + (size_t)e * 64 + h * 32);
        uint32_t vrow = vb + (uint32_t)(r * 136 + h * 64);
        #pragma unroll
        for (int i = 0; i < 8; i++) {
            float4 v = vp[i];
            sts64(vrow + (uint32_t)(i * 8), pack_h2(v.x, v.y), pack_h2(v.z, v.w));
        }
    }

    /* edge half-row -> 32 f16x2 registers */
    uint32_t xh[32];
    {
        const float4* xp = (const float4*)(xedges + (size_t)e * 128 + h * 64);
        #pragma unroll
        for (int i = 0; i < 16; i++) {
            float4 v = xp[i];
            xh[i * 2 + 0] = pack_h2(v.x, v.y);
            xh[i * 2 + 1] = pack_h2(v.z, v.w);
        }
    }

    /* swizzled A offsets for this (r,h): 8 x 16B slots within one 128B atom row */
    uint32_t offs[8];
    {
        uint32_t ob = (uint32_t)(((r >> 3) + h * 16) * 1024 + (r & 7) * 128);
        uint32_t rs = (uint32_t)(r & 7);
        #pragma unroll
        for (int i = 0; i < 8; i++)
            offs[i] = ob + ((((uint32_t)i) ^ rs) << 4);
    }
    __syncthreads();   /* vertices staged, mbarriers live */

    /* smem desc base: SW128, version=1, SBO=64, LBO=1 */
    const uint64_t DBASE = (uint64_t(2) << 61) | (uint64_t(1) << 46) |
                           (uint64_t(64) << 32) | (uint64_t(1) << 16);
    const uint32_t vrow32 = vb + (uint32_t)(r * 136);

    int s3 = 0, p3 = 0, s4 = 0, p4 = 0;

    for (int j = 0; j < NCHUNK; j++) {
        /* A slot s3 reuse gate: commit of chunk j-3 */
        if (j >= 3) mbar_wait(base + SM_MB_D + s3 * 8, (uint32_t)(p3 ^ 1));

        const uint32_t aAddr = base + SM_A + (uint32_t)s3 * A_TILE;

        if (j < 64) {
            /* broadcast vert[r][j] into f16x2 */
            uint32_t w  = lds32(vrow32 + (uint32_t)((j >> 1) << 2));
            uint32_t ct = (j & 1) ? 0x3232u : 0x1010u;
            uint32_t sv;
            asm("prmt.b32 %0, %1, %1, %2;" : "=r"(sv) : "r"(w), "r"(ct));
            #pragma unroll
            for (int i = 0; i < 8; i++) {
                sts128(aAddr + offs[i],
                       hmul2(xh[i * 4 + 0], sv), hmul2(xh[i * 4 + 1], sv),
                       hmul2(xh[i * 4 + 2], sv), hmul2(xh[i * 4 + 3], sv));
            }
        } else {
            /* bias chunk: A[e,k] = (k<64)? fp16(vert[e,k]) : 0 */
            if (h == 0) {
                #pragma unroll
                for (int i = 0; i < 8; i++) {
                    uint32_t a0, a1, a2, a3;
                    lds64(a0, a1, vrow32 + (uint32_t)(i * 16));
                    lds64(a2, a3, vrow32 + (uint32_t)(i * 16 + 8));
                    sts128(aAddr + offs[i], a0, a1, a2, a3);
                }
            } else {
                #pragma unroll
                for (int i = 0; i < 8; i++)
                    sts128(aAddr + offs[i], 0u, 0u, 0u, 0u);
            }
        }
        asm volatile("fence.proxy.async.shared::cta;" ::: "memory");
        asm volatile("mbarrier.arrive.shared.b64 _, [%0];"
                     :: "r"(base + SM_MB_A + s3 * 8) : "memory");

        if (is_elect) {
            mbar_wait(base + SM_MB_A + s3 * 8, (uint32_t)p3);       /* A(j) written   */
            mbar_wait(base + SM_MB_B + s4 * 8, (uint32_t)p4);       /* W(j) resident  */

            const uint64_t adesc = DBASE | ((uint64_t)(aAddr >> 4) & 0x3FFFull);
            const uint64_t bdesc = DBASE |
                ((uint64_t)((base + SM_B + (uint32_t)s4 * B_TILE) >> 4) & 0x3FFFull);
            #pragma unroll
            for (int kk = 0; kk < 8; kk++) {
                uint64_t ad = adesc + (uint64_t)((kk >> 2) * 1024 + (kk & 3) * 2);
                uint64_t bd = bdesc + (uint64_t)((kk >> 2) * 512  + (kk & 3) * 2);
                uint32_t en = ((j > 0) || (kk > 0)) ? 1u : 0u;
                asm volatile(
                    "{\n\t.reg .pred p;\n\tsetp.ne.u32 p, %5, 0;\n\t"
                    "tcgen05.mma.cta_group::1.kind::f16 [%0], %1, %2, %3, {%4, %4, %4, %4}, p;\n\t}"
                    :: "r"(tmem), "l"(ad), "l"(bd), "r"(0x08100010u), "r"(0u), "r"(en) : "memory");
            }
            asm volatile("tcgen05.commit.cta_group::1.mbarrier::arrive::one.shared::cluster.b64 [%0];"
                         :: "r"(base + SM_MB_D + s3 * 8) : "memory");
            int nj = j + 2;
            if (nj < NCHUNK) {
                uint32_t bs = (uint32_t)((s4 + 2) & 3);
                asm volatile("mbarrier.arrive.expect_tx.shared.b64 _, [%0], %1;"
                             :: "r"(base + SM_MB_B + bs * 8), "r"((uint32_t)B_TILE) : "memory");
                asm volatile("cp.async.bulk.shared::cta.global.mbarrier::complete_tx::bytes [%0], [%1], %2, [%3];"
                             :: "r"(base + SM_B + bs * B_TILE),
                                "l"(g_Wimg + (size_t)nj * B_TILE),
                                "r"((uint32_t)B_TILE),
                                "r"(base + SM_MB_B + bs * 8) : "memory");
            }
        }
        if (++s3 == 3) { s3 = 0; p3 ^= 1; }
        if (++s4 == 4) { s4 = 0; p4 ^= 1; }
    }

    /* wait for last chunk's MMAs, read D, store */
    mbar_wait(base + SM_MB_D + LAST_S * 8, (uint32_t)LAST_P);
    asm volatile("tcgen05.fence::after_thread_sync;" ::: "memory");

    if (wid < 4) {
        uint32_t d[64];
        #pragma unroll
        for (int hb = 0; hb < 2; hb++) {
            uint32_t* rr = d + hb * 32;
            asm volatile(
                "tcgen05.ld.sync.aligned.32x32b.x32.b32 "
                "{%0, %1, %2, %3, %4, %5, %6, %7, "
                " %8, %9, %10, %11, %12, %13, %14, %15, "
                " %16, %17, %18, %19, %20, %21, %22, %23, "
                " %24, %25, %26, %27, %28, %29, %30, %31}, [%32];"
                : "=r"(rr[0]),  "=r"(rr[1]),  "=r"(rr[2]),  "=r"(rr[3]),
                  "=r"(rr[4]),  "=r"(rr[5]),  "=r"(rr[6]),  "=r"(rr[7]),
                  "=r"(rr[8]),  "=r"(rr[9]),  "=r"(rr[10]), "=r"(rr[11]),
                  "=r"(rr[12]), "=r"(rr[13]), "=r"(rr[14]), "=r"(rr[15]),
                  "=r"(rr[16]), "=r"(rr[17]), "=r"(rr[18]), "=r"(rr[19]),
                  "=r"(rr[20]), "=r"(rr[21]), "=r"(rr[22]), "=r"(rr[23]),
                  "=r"(rr[24]), "=r"(rr[25]), "=r"(rr[26]), "=r"(rr[27]),
                  "=r"(rr[28]), "=r"(rr[29]), "=r"(rr[30]), "=r"(rr[31])
                : "r"(tmem + hb * 32));
        }
        asm volatile("tcgen05.wait::ld.sync.aligned;" ::: "memory");
        int eo = tb + wid * 32 + lane;
        if (eo < E_TOT) {
            float4* dst = (float4*)(out + (size_t)eo * 64);
            #pragma unroll
            for (int c4 = 0; c4 < 16; c4++) {
                float4 v;
                v.x = __uint_as_float(d[c4 * 4 + 0]);
                v.y = __uint_as_float(d[c4 * 4 + 1]);
                v.z = __uint_as_float(d[c4 * 4 + 2]);
                v.w = __uint_as_float(d[c4 * 4 + 3]);
                dst[c4] = v;
            }
        }
    }
    __syncthreads();
    if (wid == 0) {
        asm volatile("tcgen05.dealloc.cta_group::1.sync.aligned.b32 %0, 512;" :: "r"(tmem));
    }

#else
    /* ================= fallback path (plain sm_103, fp32 FFMA) ================= */
    float* Xs  = (float*)(sb + FB_X);    /* [128 k][132] */
    float* Vs  = (float*)(sb + FB_V);    /* [64 v][132]  */
    float* Bs  = (float*)(sb + FB_B);    /* [2][64 m][132] */
    float* Bsm = (float*)(sb + FB_S);    /* [64 v][64 m] */

    for (int i = tid; i < 128 * 128; i += 256) {
        int e = i >> 7, k = i & 127;
        int ge = tb + e; if (ge >= E_TOT) ge = E_TOT - 1;
        Xs[k * 132 + e] = xedges[(size_t)ge * 128 + k];
    }
    for (int i = tid; i < 128 * 64; i += 256) {
        int e = i >> 6, v = i & 63;
        int ge = tb + e; if (ge >= E_TOT) ge = E_TOT - 1;
        Vs[v * 132 + e] = vert[(size_t)ge * 64 + v];
    }
    for (int i = tid; i < 4096; i += 256) {
        int v = i & 63, m = i >> 6;
        Bsm[v * 64 + m] = bg[m * 64 + v];
    }

    const int ebk = tid & 31;
    const int mb  = tid >> 5;
    float acc[4][8];
    #pragma unroll
    for (int i = 0; i < 4; i++)
        #pragma unroll
        for (int jj = 0; jj < 8; jj++) acc[i][jj] = 0.f;

    auto issueW = [&](int v, int buf) {
        uint32_t dbase = base + FB_B + (uint32_t)buf * 33792u;
        for (int c = tid; c < 2048; c += 256) {
            int m = c >> 5, k4 = c & 31;
            const float* src = Wg + ((size_t)(m * 64 + v)) * 128 + k4 * 4;
            uint32_t dst = dbase + (uint32_t)(m * 528 + k4 * 16);
            asm volatile("cp.async.ca.shared.global [%0], [%1], 16;" :: "r"(dst), "l"(src) : "memory");
        }
        asm volatile("cp.async.commit_group;" ::: "memory");
    };

    issueW(0, 0);
    __syncthreads();

    for (int v = 0; v < 64; v++) {
        int buf = v & 1;
        if (v + 1 < 64) {
            issueW(v + 1, buf ^ 1);
            asm volatile("cp.async.wait_group 1;" ::: "memory");
        } else {
            asm volatile("cp.async.wait_group 0;" ::: "memory");
        }
        __syncthreads();

        float4 vsv = *(const float4*)(Vs + v * 132 + ebk * 4);
        const float* Bv = Bs + (size_t)buf * 8448 + (size_t)mb * 8 * 132;

        for (int k = 0; k < 128; k++) {
            float4 x4 = *(const float4*)(Xs + k * 132 + ebk * 4);
            float xa0 = x4.x * vsv.x, xa1 = x4.y * vsv.y;
            float xa2 = x4.z * vsv.z, xa3 = x4.w * vsv.w;
            #pragma unroll
            for (int jj = 0; jj < 8; jj++) {
                float bvj = Bv[jj * 132 + k];
                acc[0][jj] += xa0 * bvj;
                acc[1][jj] += xa1 * bvj;
                acc[2][jj] += xa2 * bvj;
                acc[3][jj] += xa3 * bvj;
            }
        }
        __syncthreads();
    }

    for (int v = 0; v < 64; v++) {
        float4 vsv = *(const float4*)(Vs + v * 132 + ebk * 4);
        #pragma unroll
        for (int jj = 0; jj < 8; jj++) {
            float bb = Bsm[v * 64 + mb * 8 + jj];
            acc[0][jj] += vsv.x * bb;
            acc[1][jj] += vsv.y * bb;
            acc[2][jj] += vsv.z * bb;
            acc[3][jj] += vsv.w * bb;
        }
    }

    #pragma unroll
    for (int i = 0; i < 4; i++) {
        int e = tb + ebk * 4 + i;
        if (e < E_TOT) {
            #pragma unroll
            for (int jj = 0; jj < 8; jj++)
                out[(size_t)e * 64 + mb * 8 + jj] = acc[i][jj];
        }
    }
#endif
}

/* ---------------- launcher ---------------- */
extern "C" void kernel_launch(void* const* d_in, const int* in_sizes, int n_in,
                              void* d_out, int out_size) {
    const float* vert  = (const float*)d_in[0];  /* [100000, 64]  */
    const float* edges = (const float*)d_in[1];  /* [100000, 128] */
    const float* W     = (const float*)d_in[2];  /* [4096, 128]   */
    const float* b     = (const float*)d_in[3];  /* [4096]        */
    float* out = (float*)d_out;                  /* [100000, 64]  */

    prep_w<<<1040, 256>>>(W, b);

    cudaFuncSetAttribute(edge_msg_main, cudaFuncAttributeMaxDynamicSharedMemorySize, SMEM_DYN);
    edge_msg_main<<<NTILES, 256, SMEM_DYN>>>(vert, edges, W, b, out);
}

// round 6
// speedup vs baseline: 2.6046x; 2.6046x over previous
#include <cuda_runtime.h>
#include <cuda_fp16.h>
#include <cstdint>

#define E_TOT      100000
#define NCHUNK     65
#define B_TILE     16384
#define NTILES     782          /* ceil(100000/128) */

/* ---- tcgen05-path smem layout (relative to 1024-aligned base) ---- */
#define SM_B       0            /* 4 x 16384 = 65536 : W ring            */
#define SM_V       65536        /* 128 rows x 132 B fp16 vert = 16896    */
#define SM_TPTR    82432
#define SM_MB_D    82448        /* 2 x 8B : mma committed (A-buf gate) */
#define SM_MB_B    82464        /* 4 x 8B : W-chunk full               */
#define SM_END     82496

#define SMEM_DYN   (SM_END + 1024)   /* 83520: fits 2 CTAs/SM */

/* TMEM column map (alloc 256): D = [0,64), A buf0 = [64,128), A buf1 = [128,192) */
#define TM_D       0
#define TM_A       64

/* ---- fallback-path smem layout (never executed on sm_103a; compile-only) ---- */
#define FB_X       0
#define FB_V       67584
#define FB_B       101376
#define FB_S       168960

/* does this device pass have tcgen05 (arch-specific sm_103a/sm_100a)? */
#if !defined(__CUDA_ARCH__)
#  define TCPATH 1   /* host pass: parse the tcgen05 branch (not codegen'd) */
#elif defined(__CUDA_ARCH_FEAT_SM103_ALL) || defined(__CUDA_ARCH_FEAT_SM100_ALL) || \
      defined(__CUDA_ARCH_FEAT_SM101_ALL) || defined(__CUDA_ARCH_SPECIFIC__)
#  define TCPATH 1
#else
#  define TCPATH 0
#endif

/* pre-swizzled fp16 W' image: 65 chunks of [64 n x 128 k] blocked SW128 */
__device__ __align__(16) unsigned char g_Wimg[NCHUNK * B_TILE];

/* ---------------- generic helpers ---------------- */

__device__ __forceinline__ uint32_t sw128(uint32_t x) { return x ^ ((x >> 3) & 0x70u); }

__device__ __forceinline__ uint32_t smem_u32(const void* p) {
    uint32_t a;
    asm("{ .reg .u64 t; cvta.to.shared.u64 t, %1; cvt.u32.u64 %0, t; }" : "=r"(a) : "l"(p));
    return a;
}

/* pack two f32 -> f16x2; 'lo' lands in the low (memory-first) half */
__device__ __forceinline__ uint32_t pack_h2(float lo, float hi) {
    uint32_t r;
    asm("cvt.rn.f16x2.f32 %0, %1, %2;" : "=r"(r) : "f"(hi), "f"(lo));
    return r;
}

__device__ __forceinline__ uint32_t hmul2(uint32_t a, uint32_t b) {
    uint32_t r;
    asm("mul.rn.f16x2 %0, %1, %2;" : "=r"(r) : "r"(a), "r"(b));
    return r;
}

__device__ __forceinline__ void sts32(uint32_t addr, uint32_t a) {
    asm volatile("st.shared.b32 [%0], %1;" :: "r"(addr), "r"(a) : "memory");
}
__device__ __forceinline__ uint32_t lds32(uint32_t addr) {
    uint32_t v;
    asm volatile("ld.shared.b32 %0, [%1];" : "=r"(v) : "r"(addr));
    return v;
}

__device__ __forceinline__ void mbar_wait(uint32_t mbar, uint32_t parity) {
    asm volatile(
        "{\n\t.reg .pred P;\n\tWL_%=:\n\t"
        "mbarrier.try_wait.parity.acquire.cta.shared::cta.b64 P, [%0], %1, 0x989680;\n\t"
        "@P bra.uni WD_%=;\n\tbra.uni WL_%=;\n\tWD_%=:\n\t}"
        :: "r"(mbar), "r"(parity) : "memory");
}

#if TCPATH
/* store 16 b32 to 16 consecutive TMEM columns (warp-collective) */
__device__ __forceinline__ void sttm_x16(uint32_t addr, const uint32_t* t) {
    asm volatile(
        "tcgen05.st.sync.aligned.32x32b.x16.b32 [%0], "
        "{%1, %2, %3, %4, %5, %6, %7, %8, "
        " %9, %10, %11, %12, %13, %14, %15, %16};"
        :: "r"(addr),
           "r"(t[0]),  "r"(t[1]),  "r"(t[2]),  "r"(t[3]),
           "r"(t[4]),  "r"(t[5]),  "r"(t[6]),  "r"(t[7]),
           "r"(t[8]),  "r"(t[9]),  "r"(t[10]), "r"(t[11]),
           "r"(t[12]), "r"(t[13]), "r"(t[14]), "r"(t[15])
        : "memory");
}
#endif

/* ---------------- prep kernel: pre-swizzled fp16 W' image ---------------- */
/* chunk c<64: Wc[n,k] = W[n*64+c, k]; chunk 64: Wc[n,k] = (k<64)? b[n*64+k] : 0 */
__global__ void prep_w(const float* __restrict__ W, const float* __restrict__ b) {
    uint32_t gid = blockIdx.x * 256u + threadIdx.x;      /* 0 .. 266239 */
    uint32_t c  = gid >> 12;
    uint32_t r  = gid & 4095u;
    uint32_t n  = r >> 6;
    uint32_t k  = (r & 63u) * 2u;
    float w0, w1;
    if (c < 64u) {
        const float* s = W + ((n * 64u + c) * 128u + k);
        w0 = s[0]; w1 = s[1];
    } else if (k < 64u) {
        w0 = b[n * 64u + k]; w1 = b[n * 64u + k + 1u];
    } else {
        w0 = 0.f; w1 = 0.f;
    }
    uint32_t off = ((n >> 3) + (k >> 6) * 8u) * 1024u + (n & 7u) * 128u + (k & 63u) * 2u;
    *(uint32_t*)(g_Wimg + c * B_TILE + sw128(off)) = pack_h2(w0, w1);
}

/* ---------------- main kernel ---------------- */
__global__ void __launch_bounds__(256, 2)
edge_msg_main(const float* __restrict__ vert,
              const float* __restrict__ xedges,
              const float* __restrict__ Wg,
              const float* __restrict__ bg,
              float* __restrict__ out)
{
    extern __shared__ unsigned char smem_raw[];
    const uint32_t raw  = smem_u32(smem_raw);
    const uint32_t base = (raw + 1023u) & ~1023u;
    unsigned char* sb   = smem_raw + (base - raw);

    const int tid  = threadIdx.x;
    const int tb   = blockIdx.x * 128;

#if TCPATH
    /* ================= tcgen05 path (sm_103a, TS-mode A in TMEM) ================= */
    const int wid    = tid >> 5;
    const int lane   = tid & 31;
    const int wg     = tid >> 7;       /* K-half owner: 0 -> k[0,64), 1 -> k[64,128) */
    const int wg_tid = tid & 127;
    const int r      = wg_tid;         /* owned A row (M index) */

    (void)Wg; (void)bg; (void)sb;

    if (tid == 0) {
        #pragma unroll
        for (int i = 0; i < 2; i++)
            asm volatile("mbarrier.init.shared.b64 [%0], 1;" :: "r"(base + SM_MB_D + i * 8) : "memory");
        #pragma unroll
        for (int i = 0; i < 4; i++)
            asm volatile("mbarrier.init.shared.b64 [%0], 1;" :: "r"(base + SM_MB_B + i * 8) : "memory");
    }
    if (wid == 0) {
        asm volatile("tcgen05.alloc.cta_group::1.sync.aligned.shared::cta.b32 [%0], 256;"
                     :: "r"(base + SM_TPTR) : "memory");
        asm volatile("tcgen05.relinquish_alloc_permit.cta_group::1.sync.aligned;");
    }
    __syncthreads();
    uint32_t tmem;
    asm volatile("ld.shared.b32 %0, [%1];" : "=r"(tmem) : "r"(base + SM_TPTR));

    bool is_elect = false;
    {
        uint32_t p;
        asm volatile("{\n\t.reg .pred P;\n\telect.sync _|P, 0xFFFFFFFF;\n\tselp.b32 %0, 1, 0, P;\n\t}" : "=r"(p));
        is_elect = (wid == 0) && (p != 0);
    }

    /* prefetch W chunks 0,1 */
    if (is_elect) {
        #pragma unroll
        for (int j = 0; j < 2; j++) {
            asm volatile("mbarrier.arrive.expect_tx.shared.b64 _, [%0], %1;"
                         :: "r"(base + SM_MB_B + j * 8), "r"((uint32_t)B_TILE) : "memory");
            asm volatile("cp.async.bulk.shared::cta.global.mbarrier::complete_tx::bytes [%0], [%1], %2, [%3];"
                         :: "r"(base + SM_B + j * B_TILE), "l"(g_Wimg + j * B_TILE),
                            "r"((uint32_t)B_TILE), "r"(base + SM_MB_B + j * 8) : "memory");
        }
    }

    int e = tb + r; if (e >= E_TOT) e = E_TOT - 1;

    /* stage vertices as fp16: V[r][64], row stride 132 B (33 words: conflict-free).
       4-byte scalar shared ops only (132 is not 8/16-aligned per row). */
    const uint32_t vb    = base + SM_V;
    const uint32_t vrow  = vb + (uint32_t)(r * 132);
    {
        const float4* vp = (const float4*)(vert + (size_t)e * 64 + wg * 32);
        uint32_t dst = vrow + (uint32_t)(wg * 64);
        #pragma unroll
        for (int i = 0; i < 8; i++) {
            float4 v = vp[i];
            sts32(dst + (uint32_t)(i * 8),     pack_h2(v.x, v.y));
            sts32(dst + (uint32_t)(i * 8 + 4), pack_h2(v.z, v.w));
        }
    }

    /* edge half-row -> 32 f16x2 registers: xh[c] holds k = wg*64 + 2c, 2c+1 */
    uint32_t xh[32];
    {
        const float4* xp = (const float4*)(xedges + (size_t)e * 128 + wg * 64);
        #pragma unroll
        for (int i = 0; i < 16; i++) {
            float4 v = xp[i];
            xh[i * 2 + 0] = pack_h2(v.x, v.y);
            xh[i * 2 + 1] = pack_h2(v.z, v.w);
        }
    }

    /* this thread's A TMEM address base: col = wg*32, warp subpartition in bits 21+ */
    const uint32_t warp_off = ((uint32_t)(wg_tid >> 5)) << 21;
    const uint32_t aTBase   = tmem + TM_A + (uint32_t)(wg * 32) + warp_off;

    __syncthreads();   /* vertices staged, mbarriers live, TMEM ptr read */

    /* smem desc base: SW128, version=1, SBO=64, LBO=1 */
    const uint64_t DBASE = (uint64_t(2) << 61) | (uint64_t(1) << 46) |
                           (uint64_t(64) << 32) | (uint64_t(1) << 16);

    for (int j = 0; j < NCHUNK; j++) {
        const uint32_t abuf = (uint32_t)(j & 1) * 64u;

        /* A-buf reuse gate: MMA(j-2) complete. Elect checks; BAR broadcasts. */
        if (is_elect && j >= 2)
            mbar_wait(base + SM_MB_D + (j & 1) * 8, (uint32_t)(((j >> 1) ^ 1) & 1));
        __syncthreads();

        /* synthesize A(j) straight into TMEM */
        if (j < 64) {
            uint32_t w  = lds32(vrow + (uint32_t)((j >> 1) << 2));
            uint32_t ct = (j & 1) ? 0x3232u : 0x1010u;
            uint32_t sv;
            asm("prmt.b32 %0, %1, %1, %2;" : "=r"(sv) : "r"(w), "r"(ct));
            uint32_t t[16];
            #pragma unroll
            for (int i = 0; i < 16; i++) t[i] = hmul2(xh[i], sv);
            sttm_x16(aTBase + abuf, t);
            #pragma unroll
            for (int i = 0; i < 16; i++) t[i] = hmul2(xh[16 + i], sv);
            sttm_x16(aTBase + abuf + 16, t);
        } else {
            /* bias chunk: A[e,k] = (k<64)? fp16(vert[e,k]) : 0 */
            uint32_t t[16];
            if (wg == 0) {
                #pragma unroll
                for (int i = 0; i < 16; i++) t[i] = lds32(vrow + (uint32_t)(i * 4));
                sttm_x16(aTBase + abuf, t);
                #pragma unroll
                for (int i = 0; i < 16; i++) t[i] = lds32(vrow + (uint32_t)(64 + i * 4));
                sttm_x16(aTBase + abuf + 16, t);
            } else {
                #pragma unroll
                for (int i = 0; i < 16; i++) t[i] = 0u;
                sttm_x16(aTBase + abuf, t);
                sttm_x16(aTBase + abuf + 16, t);
            }
        }
        asm volatile("tcgen05.wait::st.sync.aligned;" ::: "memory");
        asm volatile("tcgen05.fence::before_thread_sync;" ::: "memory");
        __syncthreads();

        if (is_elect) {
            asm volatile("tcgen05.fence::after_thread_sync;" ::: "memory");
            const int s4 = j & 3;
            mbar_wait(base + SM_MB_B + s4 * 8, (uint32_t)((j >> 2) & 1));

            const uint64_t bdesc = DBASE |
                ((uint64_t)((base + SM_B + (uint32_t)s4 * B_TILE) >> 4) & 0x3FFFull);
            const uint32_t aMma = tmem + TM_A + abuf;
            #pragma unroll
            for (int kk = 0; kk < 8; kk++) {
                uint64_t bd = bdesc + (uint64_t)((kk >> 2) * 512 + (kk & 3) * 2);
                uint32_t at = aMma + (uint32_t)(kk * 8);
                uint32_t en = ((j > 0) || (kk > 0)) ? 1u : 0u;
                asm volatile(
                    "{\n\t.reg .pred p;\n\tsetp.ne.u32 p, %5, 0;\n\t"
                    "tcgen05.mma.cta_group::1.kind::f16 [%0], [%1], %2, %3, {%4, %4, %4, %4}, p;\n\t}"
                    :: "r"(tmem + TM_D), "r"(at), "l"(bd), "r"(0x08100010u), "r"(0u), "r"(en)
                    : "memory");
            }
            asm volatile("tcgen05.commit.cta_group::1.mbarrier::arrive::one.shared::cluster.b64 [%0];"
                         :: "r"(base + SM_MB_D + (j & 1) * 8) : "memory");
            int nj = j + 2;
            if (nj < NCHUNK) {
                /* slot (nj&3) was last read by MMA(j-2), gated complete above */
                uint32_t bs = (uint32_t)(nj & 3);
                asm volatile("mbarrier.arrive.expect_tx.shared.b64 _, [%0], %1;"
                             :: "r"(base + SM_MB_B + bs * 8), "r"((uint32_t)B_TILE) : "memory");
                asm volatile("cp.async.bulk.shared::cta.global.mbarrier::complete_tx::bytes [%0], [%1], %2, [%3];"
                             :: "r"(base + SM_B + bs * B_TILE),
                                "l"(g_Wimg + (size_t)nj * B_TILE),
                                "r"((uint32_t)B_TILE),
                                "r"(base + SM_MB_B + bs * 8) : "memory");
            }
        }
    }

    /* wait for last chunk's MMAs (j=64: slot 0, completion #33 -> parity 0) */
    mbar_wait(base + SM_MB_D + ((NCHUNK - 1) & 1) * 8, (uint32_t)(((NCHUNK - 1) >> 1) & 1));
    asm volatile("tcgen05.fence::after_thread_sync;" ::: "memory");

    if (wid < 4) {
        uint32_t d[64];
        #pragma unroll
        for (int hb = 0; hb < 2; hb++) {
            uint32_t* rr = d + hb * 32;
            asm volatile(
                "tcgen05.ld.sync.aligned.32x32b.x32.b32 "
                "{%0, %1, %2, %3, %4, %5, %6, %7, "
                " %8, %9, %10, %11, %12, %13, %14, %15, "
                " %16, %17, %18, %19, %20, %21, %22, %23, "
                " %24, %25, %26, %27, %28, %29, %30, %31}, [%32];"
                : "=r"(rr[0]),  "=r"(rr[1]),  "=r"(rr[2]),  "=r"(rr[3]),
                  "=r"(rr[4]),  "=r"(rr[5]),  "=r"(rr[6]),  "=r"(rr[7]),
                  "=r"(rr[8]),  "=r"(rr[9]),  "=r"(rr[10]), "=r"(rr[11]),
                  "=r"(rr[12]), "=r"(rr[13]), "=r"(rr[14]), "=r"(rr[15]),
                  "=r"(rr[16]), "=r"(rr[17]), "=r"(rr[18]), "=r"(rr[19]),
                  "=r"(rr[20]), "=r"(rr[21]), "=r"(rr[22]), "=r"(rr[23]),
                  "=r"(rr[24]), "=r"(rr[25]), "=r"(rr[26]), "=r"(rr[27]),
                  "=r"(rr[28]), "=r"(rr[29]), "=r"(rr[30]), "=r"(rr[31])
                : "r"(tmem + TM_D + hb * 32));
        }
        asm volatile("tcgen05.wait::ld.sync.aligned;" ::: "memory");
        int eo = tb + wid * 32 + lane;
        if (eo < E_TOT) {
            float4* dst = (float4*)(out + (size_t)eo * 64);
            #pragma unroll
            for (int c4 = 0; c4 < 16; c4++) {
                float4 v;
                v.x = __uint_as_float(d[c4 * 4 + 0]);
                v.y = __uint_as_float(d[c4 * 4 + 1]);
                v.z = __uint_as_float(d[c4 * 4 + 2]);
                v.w = __uint_as_float(d[c4 * 4 + 3]);
                dst[c4] = v;
            }
        }
    }
    __syncthreads();
    if (wid == 0) {
        asm volatile("tcgen05.dealloc.cta_group::1.sync.aligned.b32 %0, 256;" :: "r"(tmem));
    }

#else
    /* ================= fallback path (plain sm_103; compile-only on this target,
       the sm_103a SASS is always selected at load time on GB300) ================= */
    float* Xs  = (float*)(sb + FB_X);
    float* Vs  = (float*)(sb + FB_V);
    float* Bs  = (float*)(sb + FB_B);
    float* Bsm = (float*)(sb + FB_S);

    for (int i = tid; i < 128 * 128; i += 256) {
        int e2 = i >> 7, k = i & 127;
        int ge = tb + e2; if (ge >= E_TOT) ge = E_TOT - 1;
        Xs[k * 132 + e2] = xedges[(size_t)ge * 128 + k];
    }
    for (int i = tid; i < 128 * 64; i += 256) {
        int e2 = i >> 6, v = i & 63;
        int ge = tb + e2; if (ge >= E_TOT) ge = E_TOT - 1;
        Vs[v * 132 + e2] = vert[(size_t)ge * 64 + v];
    }
    for (int i = tid; i < 4096; i += 256) {
        int v = i & 63, m = i >> 6;
        Bsm[v * 64 + m] = bg[m * 64 + v];
    }

    const int ebk = tid & 31;
    const int mb  = tid >> 5;
    float acc[4][8];
    #pragma unroll
    for (int i = 0; i < 4; i++)
        #pragma unroll
        for (int jj = 0; jj < 8; jj++) acc[i][jj] = 0.f;

    auto issueW = [&](int v, int buf) {
        uint32_t dbase = base + FB_B + (uint32_t)buf * 33792u;
        for (int c = tid; c < 2048; c += 256) {
            int m = c >> 5, k4 = c & 31;
            const float* src = Wg + ((size_t)(m * 64 + v)) * 128 + k4 * 4;
            uint32_t dst = dbase + (uint32_t)(m * 528 + k4 * 16);
            asm volatile("cp.async.ca.shared.global [%0], [%1], 16;" :: "r"(dst), "l"(src) : "memory");
        }
        asm volatile("cp.async.commit_group;" ::: "memory");
    };

    issueW(0, 0);
    __syncthreads();

    for (int v = 0; v < 64; v++) {
        int buf = v & 1;
        if (v + 1 < 64) {
            issueW(v + 1, buf ^ 1);
            asm volatile("cp.async.wait_group 1;" ::: "memory");
        } else {
            asm volatile("cp.async.wait_group 0;" ::: "memory");
        }
        __syncthreads();

        float4 vsv = *(const float4*)(Vs + v * 132 + ebk * 4);
        const float* Bv = Bs + (size_t)buf * 8448 + (size_t)mb * 8 * 132;

        for (int k = 0; k < 128; k++) {
            float4 x4 = *(const float4*)(Xs + k * 132 + ebk * 4);
            float xa0 = x4.x * vsv.x, xa1 = x4.y * vsv.y;
            float xa2 = x4.z * vsv.z, xa3 = x4.w * vsv.w;
            #pragma unroll
            for (int jj = 0; jj < 8; jj++) {
                float bvj = Bv[jj * 132 + k];
                acc[0][jj] += xa0 * bvj;
                acc[1][jj] += xa1 * bvj;
                acc[2][jj] += xa2 * bvj;
                acc[3][jj] += xa3 * bvj;
            }
        }
        __syncthreads();
    }

    for (int v = 0; v < 64; v++) {
        float4 vsv = *(const float4*)(Vs + v * 132 + ebk * 4);
        #pragma unroll
        for (int jj = 0; jj < 8; jj++) {
            float bb = Bsm[v * 64 + mb * 8 + jj];
            acc[0][jj] += vsv.x * bb;
            acc[1][jj] += vsv.y * bb;
            acc[2][jj] += vsv.z * bb;
            acc[3][jj] += vsv.w * bb;
        }
    }

    #pragma unroll
    for (int i = 0; i < 4; i++) {
        int e2 = tb + ebk * 4 + i;
        if (e2 < E_TOT) {
            #pragma unroll
            for (int jj = 0; jj < 8; jj++)
                out[(size_t)e2 * 64 + mb * 8 + jj] = acc[i][jj];
        }
    }
#endif
}

/* ---------------- launcher ---------------- */
extern "C" void kernel_launch(void* const* d_in, const int* in_sizes, int n_in,
                              void* d_out, int out_size) {
    const float* vert  = (const float*)d_in[0];  /* [100000, 64]  */
    const float* edges = (const float*)d_in[1];  /* [100000, 128] */
    const float* W     = (const float*)d_in[2];  /* [4096, 128]   */
    const float* b     = (const float*)d_in[3];  /* [4096]        */
    float* out = (float*)d_out;                  /* [100000, 64]  */

    prep_w<<<1040, 256>>>(W, b);

    cudaFuncSetAttribute(edge_msg_main, cudaFuncAttributeMaxDynamicSharedMemorySize, SMEM_DYN);
    edge_msg_main<<<NTILES, 256, SMEM_DYN>>>(vert, edges, W, b, out);
}

// round 7
// speedup vs baseline: 2.7252x; 1.0463x over previous
#include <cuda_runtime.h>
#include <cuda_fp16.h>
#include <cstdint>

#define E_TOT      100000
#define NCHUNK     65
#define B_TILE     16384
#define NTILES     782          /* ceil(100000/128) */

/* ---- tcgen05-path smem layout (relative to 1024-aligned base) ---- */
#define SM_B       0            /* 4 x 16384 = 65536 : W ring            */
#define SM_V       65536        /* 128 rows x 132 B fp16 vert = 16896    */
#define SM_TPTR    82432
#define SM_MB_D    82448        /* 3 x 8B : mma committed (A-buf gate) */
#define SM_MB_A    82472        /* 3 x 8B : A-buf full (count 8)       */
#define SM_MB_B    82496        /* 4 x 8B : W-chunk full               */
#define SM_END     82528

#define SMEM_DYN   (SM_END + 1024)   /* fits 2 CTAs/SM */

/* TMEM column map (alloc 256): D = [0,64), A bufs at 64 / 128 / 192 */
#define TM_D       0
#define TM_A       64

/* last chunk j=64: D slot 64%3=1, completion 64/3=21 -> parity 1 */
#define LAST_S     1
#define LAST_P     1

/* ---- fallback-path smem layout (never executed on sm_103a; compile-only) ---- */
#define FB_X       0
#define FB_V       67584
#define FB_B       101376
#define FB_S       168960

/* does this device pass have tcgen05 (arch-specific sm_103a/sm_100a)? */
#if !defined(__CUDA_ARCH__)
#  define TCPATH 1   /* host pass: parse the tcgen05 branch (not codegen'd) */
#elif defined(__CUDA_ARCH_FEAT_SM103_ALL) || defined(__CUDA_ARCH_FEAT_SM100_ALL) || \
      defined(__CUDA_ARCH_FEAT_SM101_ALL) || defined(__CUDA_ARCH_SPECIFIC__)
#  define TCPATH 1
#else
#  define TCPATH 0
#endif

/* pre-swizzled fp16 W' image: 65 chunks of [64 n x 128 k] blocked SW128 */
__device__ __align__(16) unsigned char g_Wimg[NCHUNK * B_TILE];

/* ---------------- generic helpers ---------------- */

__device__ __forceinline__ uint32_t sw128(uint32_t x) { return x ^ ((x >> 3) & 0x70u); }

__device__ __forceinline__ uint32_t smem_u32(const void* p) {
    uint32_t a;
    asm("{ .reg .u64 t; cvta.to.shared.u64 t, %1; cvt.u32.u64 %0, t; }" : "=r"(a) : "l"(p));
    return a;
}

/* pack two f32 -> f16x2; 'lo' lands in the low (memory-first) half */
__device__ __forceinline__ uint32_t pack_h2(float lo, float hi) {
    uint32_t r;
    asm("cvt.rn.f16x2.f32 %0, %1, %2;" : "=r"(r) : "f"(hi), "f"(lo));
    return r;
}

__device__ __forceinline__ uint32_t hmul2(uint32_t a, uint32_t b) {
    uint32_t r;
    asm("mul.rn.f16x2 %0, %1, %2;" : "=r"(r) : "r"(a), "r"(b));
    return r;
}

__device__ __forceinline__ void sts32(uint32_t addr, uint32_t a) {
    asm volatile("st.shared.b32 [%0], %1;" :: "r"(addr), "r"(a) : "memory");
}
__device__ __forceinline__ uint32_t lds32(uint32_t addr) {
    uint32_t v;
    asm volatile("ld.shared.b32 %0, [%1];" : "=r"(v) : "r"(addr));
    return v;
}

__device__ __forceinline__ void mbar_wait(uint32_t mbar, uint32_t parity) {
    asm volatile(
        "{\n\t.reg .pred P;\n\tWL_%=:\n\t"
        "mbarrier.try_wait.parity.acquire.cta.shared::cta.b64 P, [%0], %1, 0x989680;\n\t"
        "@P bra.uni WD_%=;\n\tbra.uni WL_%=;\n\tWD_%=:\n\t}"
        :: "r"(mbar), "r"(parity) : "memory");
}

#if TCPATH
/* store 16 b32 to 16 consecutive TMEM columns (warp-collective) */
__device__ __forceinline__ void sttm_x16(uint32_t addr, const uint32_t* t) {
    asm volatile(
        "tcgen05.st.sync.aligned.32x32b.x16.b32 [%0], "
        "{%1, %2, %3, %4, %5, %6, %7, %8, "
        " %9, %10, %11, %12, %13, %14, %15, %16};"
        :: "r"(addr),
           "r"(t[0]),  "r"(t[1]),  "r"(t[2]),  "r"(t[3]),
           "r"(t[4]),  "r"(t[5]),  "r"(t[6]),  "r"(t[7]),
           "r"(t[8]),  "r"(t[9]),  "r"(t[10]), "r"(t[11]),
           "r"(t[12]), "r"(t[13]), "r"(t[14]), "r"(t[15])
        : "memory");
}
#endif

/* ---------------- prep kernel: pre-swizzled fp16 W' image ---------------- */
/* chunk c<64: Wc[n,k] = W[n*64+c, k]; chunk 64: Wc[n,k] = (k<64)? b[n*64+k] : 0 */
__global__ void prep_w(const float* __restrict__ W, const float* __restrict__ b) {
    uint32_t gid = blockIdx.x * 256u + threadIdx.x;      /* 0 .. 266239 */
    uint32_t c  = gid >> 12;
    uint32_t r  = gid & 4095u;
    uint32_t n  = r >> 6;
    uint32_t k  = (r & 63u) * 2u;
    float w0, w1;
    if (c < 64u) {
        const float* s = W + ((n * 64u + c) * 128u + k);
        w0 = s[0]; w1 = s[1];
    } else if (k < 64u) {
        w0 = b[n * 64u + k]; w1 = b[n * 64u + k + 1u];
    } else {
        w0 = 0.f; w1 = 0.f;
    }
    uint32_t off = ((n >> 3) + (k >> 6) * 8u) * 1024u + (n & 7u) * 128u + (k & 63u) * 2u;
    *(uint32_t*)(g_Wimg + c * B_TILE + sw128(off)) = pack_h2(w0, w1);
}

/* ---------------- main kernel ---------------- */
__global__ void __launch_bounds__(256, 2)
edge_msg_main(const float* __restrict__ vert,
              const float* __restrict__ xedges,
              const float* __restrict__ Wg,
              const float* __restrict__ bg,
              float* __restrict__ out)
{
    extern __shared__ unsigned char smem_raw[];
    const uint32_t raw  = smem_u32(smem_raw);
    const uint32_t base = (raw + 1023u) & ~1023u;
    unsigned char* sb   = smem_raw + (base - raw);

    const int tid  = threadIdx.x;
    const int tb   = blockIdx.x * 128;

#if TCPATH
    /* ================= tcgen05 path (sm_103a, TS-mode A in TMEM,
       barrier-free mainloop, A ring depth 3) ================= */
    const int wid    = tid >> 5;
    const int lane   = tid & 31;
    const int wg     = tid >> 7;       /* K-half owner: 0 -> k[0,64), 1 -> k[64,128) */
    const int wg_tid = tid & 127;
    const int r      = wg_tid;         /* owned A row (M index) */

    (void)Wg; (void)bg; (void)sb;

    if (tid == 0) {
        #pragma unroll
        for (int i = 0; i < 3; i++) {
            asm volatile("mbarrier.init.shared.b64 [%0], 1;" :: "r"(base + SM_MB_D + i * 8) : "memory");
            asm volatile("mbarrier.init.shared.b64 [%0], 8;" :: "r"(base + SM_MB_A + i * 8) : "memory");
        }
        #pragma unroll
        for (int i = 0; i < 4; i++)
            asm volatile("mbarrier.init.shared.b64 [%0], 1;" :: "r"(base + SM_MB_B + i * 8) : "memory");
    }
    if (wid == 0) {
        asm volatile("tcgen05.alloc.cta_group::1.sync.aligned.shared::cta.b32 [%0], 256;"
                     :: "r"(base + SM_TPTR) : "memory");
        asm volatile("tcgen05.relinquish_alloc_permit.cta_group::1.sync.aligned;");
    }
    __syncthreads();
    uint32_t tmem;
    asm volatile("ld.shared.b32 %0, [%1];" : "=r"(tmem) : "r"(base + SM_TPTR));

    bool lane_elect = false;   /* one thread per warp */
    {
        uint32_t p;
        asm volatile("{\n\t.reg .pred P;\n\telect.sync _|P, 0xFFFFFFFF;\n\tselp.b32 %0, 1, 0, P;\n\t}" : "=r"(p));
        lane_elect = (p != 0);
    }
    const bool is_elect = (wid == 0) && lane_elect;

    /* prefetch W chunks 0,1 */
    if (is_elect) {
        #pragma unroll
        for (int j = 0; j < 2; j++) {
            asm volatile("mbarrier.arrive.expect_tx.shared.b64 _, [%0], %1;"
                         :: "r"(base + SM_MB_B + j * 8), "r"((uint32_t)B_TILE) : "memory");
            asm volatile("cp.async.bulk.shared::cta.global.mbarrier::complete_tx::bytes [%0], [%1], %2, [%3];"
                         :: "r"(base + SM_B + j * B_TILE), "l"(g_Wimg + j * B_TILE),
                            "r"((uint32_t)B_TILE), "r"(base + SM_MB_B + j * 8) : "memory");
        }
    }

    int e = tb + r; if (e >= E_TOT) e = E_TOT - 1;

    /* stage vertices as fp16: V[r][64], row stride 132 B (33 words: conflict-free).
       4-byte scalar shared ops only. */
    const uint32_t vb    = base + SM_V;
    const uint32_t vrow  = vb + (uint32_t)(r * 132);
    {
        const float4* vp = (const float4*)(vert + (size_t)e * 64 + wg * 32);
        uint32_t dst = vrow + (uint32_t)(wg * 64);
        #pragma unroll
        for (int i = 0; i < 8; i++) {
            float4 v = vp[i];
            sts32(dst + (uint32_t)(i * 8),     pack_h2(v.x, v.y));
            sts32(dst + (uint32_t)(i * 8 + 4), pack_h2(v.z, v.w));
        }
    }

    /* edge half-row -> 32 f16x2 registers: xh[c] holds k = wg*64 + 2c, 2c+1 */
    uint32_t xh[32];
    {
        const float4* xp = (const float4*)(xedges + (size_t)e * 128 + wg * 64);
        #pragma unroll
        for (int i = 0; i < 16; i++) {
            float4 v = xp[i];
            xh[i * 2 + 0] = pack_h2(v.x, v.y);
            xh[i * 2 + 1] = pack_h2(v.z, v.w);
        }
    }

    /* this thread's A TMEM address base: col = wg*32, warp subpartition in bits 21+ */
    const uint32_t warp_off = ((uint32_t)(wg_tid >> 5)) << 21;
    const uint32_t aTBase   = tmem + TM_A + (uint32_t)(wg * 32) + warp_off;

    __syncthreads();   /* vertices staged, mbarriers live, TMEM ptr read */

    /* smem desc base: SW128, version=1, SBO=64, LBO=1 */
    const uint64_t DBASE = (uint64_t(2) << 61) | (uint64_t(1) << 46) |
                           (uint64_t(64) << 32) | (uint64_t(1) << 16);

    int s3 = 0, p3 = 0;        /* j%3, (j/3)&1                     */
    int sw = 0, pw = 0;        /* (j-2)%3, ((j-2)/3)&1 (elect use) */

    for (int j = 0; j < NCHUNK; j++) {
        const uint32_t abuf = (uint32_t)s3 * 64u;

        /* A-buf reuse gate: commit of chunk j-3 (same slot, previous phase). */
        if (j >= 3) {
            mbar_wait(base + SM_MB_D + s3 * 8, (uint32_t)(p3 ^ 1));
            asm volatile("tcgen05.fence::after_thread_sync;" ::: "memory");
        }

        /* synthesize A(j) straight into TMEM */
        if (j < 64) {
            uint32_t w  = lds32(vrow + (uint32_t)((j >> 1) << 2));
            uint32_t ct = (j & 1) ? 0x3232u : 0x1010u;
            uint32_t sv;
            asm("prmt.b32 %0, %1, %1, %2;" : "=r"(sv) : "r"(w), "r"(ct));
            uint32_t t[16];
            #pragma unroll
            for (int i = 0; i < 16; i++) t[i] = hmul2(xh[i], sv);
            sttm_x16(aTBase + abuf, t);
            #pragma unroll
            for (int i = 0; i < 16; i++) t[i] = hmul2(xh[16 + i], sv);
            sttm_x16(aTBase + abuf + 16, t);
        } else {
            /* bias chunk: A[e,k] = (k<64)? fp16(vert[e,k]) : 0 */
            uint32_t t[16];
            if (wg == 0) {
                #pragma unroll
                for (int i = 0; i < 16; i++) t[i] = lds32(vrow + (uint32_t)(i * 4));
                sttm_x16(aTBase + abuf, t);
                #pragma unroll
                for (int i = 0; i < 16; i++) t[i] = lds32(vrow + (uint32_t)(64 + i * 4));
                sttm_x16(aTBase + abuf + 16, t);
            } else {
                #pragma unroll
                for (int i = 0; i < 16; i++) t[i] = 0u;
                sttm_x16(aTBase + abuf, t);
                sttm_x16(aTBase + abuf + 16, t);
            }
        }
        asm volatile("tcgen05.wait::st.sync.aligned;" ::: "memory");
        asm volatile("tcgen05.fence::before_thread_sync;" ::: "memory");
        if (lane_elect)
            asm volatile("mbarrier.arrive.shared.b64 _, [%0];"
                         :: "r"(base + SM_MB_A + s3 * 8) : "memory");

        if (is_elect) {
            /* wait all 8 warps' A writes */
            mbar_wait(base + SM_MB_A + s3 * 8, (uint32_t)p3);
            asm volatile("tcgen05.fence::after_thread_sync;" ::: "memory");
            /* wait W chunk resident */
            const int s4 = j & 3;
            mbar_wait(base + SM_MB_B + s4 * 8, (uint32_t)((j >> 2) & 1));

            const uint64_t bdesc = DBASE |
                ((uint64_t)((base + SM_B + (uint32_t)s4 * B_TILE) >> 4) & 0x3FFFull);
            const uint32_t aMma = tmem + TM_A + abuf;
            #pragma unroll
            for (int kk = 0; kk < 8; kk++) {
                uint64_t bd = bdesc + (uint64_t)((kk >> 2) * 512 + (kk & 3) * 2);
                uint32_t at = aMma + (uint32_t)(kk * 8);
                uint32_t en = ((j > 0) || (kk > 0)) ? 1u : 0u;
                asm volatile(
                    "{\n\t.reg .pred p;\n\tsetp.ne.u32 p, %5, 0;\n\t"
                    "tcgen05.mma.cta_group::1.kind::f16 [%0], [%1], %2, %3, {%4, %4, %4, %4}, p;\n\t}"
                    :: "r"(tmem + TM_D), "r"(at), "l"(bd), "r"(0x08100010u), "r"(0u), "r"(en)
                    : "memory");
            }
            asm volatile("tcgen05.commit.cta_group::1.mbarrier::arrive::one.shared::cluster.b64 [%0];"
                         :: "r"(base + SM_MB_D + s3 * 8) : "memory");

            /* refill W slot (j+2)&3; its last reader is MMA(j-2) -> gate on D(j-2) */
            int nj = j + 2;
            if (nj < NCHUNK) {
                if (j >= 2) {
                    mbar_wait(base + SM_MB_D + sw * 8, (uint32_t)pw);
                    if (++sw == 3) { sw = 0; pw ^= 1; }
                }
                uint32_t bs = (uint32_t)(nj & 3);
                asm volatile("mbarrier.arrive.expect_tx.shared.b64 _, [%0], %1;"
                             :: "r"(base + SM_MB_B + bs * 8), "r"((uint32_t)B_TILE) : "memory");
                asm volatile("cp.async.bulk.shared::cta.global.mbarrier::complete_tx::bytes [%0], [%1], %2, [%3];"
                             :: "r"(base + SM_B + bs * B_TILE),
                                "l"(g_Wimg + (size_t)nj * B_TILE),
                                "r"((uint32_t)B_TILE),
                                "r"(base + SM_MB_B + bs * 8) : "memory");
            }
        }
        if (++s3 == 3) { s3 = 0; p3 ^= 1; }
    }

    /* wait for last chunk's MMAs (j=64: slot 1, completion 21 -> parity 1) */
    mbar_wait(base + SM_MB_D + LAST_S * 8, (uint32_t)LAST_P);
    asm volatile("tcgen05.fence::after_thread_sync;" ::: "memory");

    if (wid < 4) {
        uint32_t d[64];
        #pragma unroll
        for (int hb = 0; hb < 2; hb++) {
            uint32_t* rr = d + hb * 32;
            asm volatile(
                "tcgen05.ld.sync.aligned.32x32b.x32.b32 "
                "{%0, %1, %2, %3, %4, %5, %6, %7, "
                " %8, %9, %10, %11, %12, %13, %14, %15, "
                " %16, %17, %18, %19, %20, %21, %22, %23, "
                " %24, %25, %26, %27, %28, %29, %30, %31}, [%32];"
                : "=r"(rr[0]),  "=r"(rr[1]),  "=r"(rr[2]),  "=r"(rr[3]),
                  "=r"(rr[4]),  "=r"(rr[5]),  "=r"(rr[6]),  "=r"(rr[7]),
                  "=r"(rr[8]),  "=r"(rr[9]),  "=r"(rr[10]), "=r"(rr[11]),
                  "=r"(rr[12]), "=r"(rr[13]), "=r"(rr[14]), "=r"(rr[15]),
                  "=r"(rr[16]), "=r"(rr[17]), "=r"(rr[18]), "=r"(rr[19]),
                  "=r"(rr[20]), "=r"(rr[21]), "=r"(rr[22]), "=r"(rr[23]),
                  "=r"(rr[24]), "=r"(rr[25]), "=r"(rr[26]), "=r"(rr[27]),
                  "=r"(rr[28]), "=r"(rr[29]), "=r"(rr[30]), "=r"(rr[31])
                : "r"(tmem + TM_D + hb * 32));
        }
        asm volatile("tcgen05.wait::ld.sync.aligned;" ::: "memory");
        int eo = tb + wid * 32 + lane;
        if (eo < E_TOT) {
            float4* dst = (float4*)(out + (size_t)eo * 64);
            #pragma unroll
            for (int c4 = 0; c4 < 16; c4++) {
                float4 v;
                v.x = __uint_as_float(d[c4 * 4 + 0]);
                v.y = __uint_as_float(d[c4 * 4 + 1]);
                v.z = __uint_as_float(d[c4 * 4 + 2]);
                v.w = __uint_as_float(d[c4 * 4 + 3]);
                dst[c4] = v;
            }
        }
    }
    __syncthreads();
    if (wid == 0) {
        asm volatile("tcgen05.dealloc.cta_group::1.sync.aligned.b32 %0, 256;" :: "r"(tmem));
    }

#else
    /* ================= fallback path (plain sm_103; compile-only on this target,
       the sm_103a SASS is always selected at load time on GB300) ================= */
    float* Xs  = (float*)(sb + FB_X);
    float* Vs  = (float*)(sb + FB_V);
    float* Bs  = (float*)(sb + FB_B);
    float* Bsm = (float*)(sb + FB_S);

    for (int i = tid; i < 128 * 128; i += 256) {
        int e2 = i >> 7, k = i & 127;
        int ge = tb + e2; if (ge >= E_TOT) ge = E_TOT - 1;
        Xs[k * 132 + e2] = xedges[(size_t)ge * 128 + k];
    }
    for (int i = tid; i < 128 * 64; i += 256) {
        int e2 = i >> 6, v = i & 63;
        int ge = tb + e2; if (ge >= E_TOT) ge = E_TOT - 1;
        Vs[v * 132 + e2] = vert[(size_t)ge * 64 + v];
    }
    for (int i = tid; i < 4096; i += 256) {
        int v = i & 63, m = i >> 6;
        Bsm[v * 64 + m] = bg[m * 64 + v];
    }

    const int ebk = tid & 31;
    const int mb  = tid >> 5;
    float acc[4][8];
    #pragma unroll
    for (int i = 0; i < 4; i++)
        #pragma unroll
        for (int jj = 0; jj < 8; jj++) acc[i][jj] = 0.f;

    auto issueW = [&](int v, int buf) {
        uint32_t dbase = base + FB_B + (uint32_t)buf * 33792u;
        for (int c = tid; c < 2048; c += 256) {
            int m = c >> 5, k4 = c & 31;
            const float* src = Wg + ((size_t)(m * 64 + v)) * 128 + k4 * 4;
            uint32_t dst = dbase + (uint32_t)(m * 528 + k4 * 16);
            asm volatile("cp.async.ca.shared.global [%0], [%1], 16;" :: "r"(dst), "l"(src) : "memory");
        }
        asm volatile("cp.async.commit_group;" ::: "memory");
    };

    issueW(0, 0);
    __syncthreads();

    for (int v = 0; v < 64; v++) {
        int buf = v & 1;
        if (v + 1 < 64) {
            issueW(v + 1, buf ^ 1);
            asm volatile("cp.async.wait_group 1;" ::: "memory");
        } else {
            asm volatile("cp.async.wait_group 0;" ::: "memory");
        }
        __syncthreads();

        float4 vsv = *(const float4*)(Vs + v * 132 + ebk * 4);
        const float* Bv = Bs + (size_t)buf * 8448 + (size_t)mb * 8 * 132;

        for (int k = 0; k < 128; k++) {
            float4 x4 = *(const float4*)(Xs + k * 132 + ebk * 4);
            float xa0 = x4.x * vsv.x, xa1 = x4.y * vsv.y;
            float xa2 = x4.z * vsv.z, xa3 = x4.w * vsv.w;
            #pragma unroll
            for (int jj = 0; jj < 8; jj++) {
                float bvj = Bv[jj * 132 + k];
                acc[0][jj] += xa0 * bvj;
                acc[1][jj] += xa1 * bvj;
                acc[2][jj] += xa2 * bvj;
                acc[3][jj] += xa3 * bvj;
            }
        }
        __syncthreads();
    }

    for (int v = 0; v < 64; v++) {
        float4 vsv = *(const float4*)(Vs + v * 132 + ebk * 4);
        #pragma unroll
        for (int jj = 0; jj < 8; jj++) {
            float bb = Bsm[v * 64 + mb * 8 + jj];
            acc[0][jj] += vsv.x * bb;
            acc[1][jj] += vsv.y * bb;
            acc[2][jj] += vsv.z * bb;
            acc[3][jj] += vsv.w * bb;
        }
    }

    #pragma unroll
    for (int i = 0; i < 4; i++) {
        int e2 = tb + ebk * 4 + i;
        if (e2 < E_TOT) {
            #pragma unroll
            for (int jj = 0; jj < 8; jj++)
                out[(size_t)e2 * 64 + mb * 8 + jj] = acc[i][jj];
        }
    }
#endif
}

/* ---------------- launcher ---------------- */
extern "C" void kernel_launch(void* const* d_in, const int* in_sizes, int n_in,
                              void* d_out, int out_size) {
    const float* vert  = (const float*)d_in[0];  /* [100000, 64]  */
    const float* edges = (const float*)d_in[1];  /* [100000, 128] */
    const float* W     = (const float*)d_in[2];  /* [4096, 128]   */
    const float* b     = (const float*)d_in[3];  /* [4096]        */
    float* out = (float*)d_out;                  /* [100000, 64]  */

    prep_w<<<1040, 256>>>(W, b);

    cudaFuncSetAttribute(edge_msg_main, cudaFuncAttributeMaxDynamicSharedMemorySize, SMEM_DYN);
    edge_msg_main<<<NTILES, 256, SMEM_DYN>>>(vert, edges, W, b, out);
}